// round 3
// baseline (speedup 1.0000x reference)
#include <cuda_runtime.h>

typedef unsigned long long ull;

__device__ __forceinline__ ull pack2(float lo, float hi) {
    ull r; asm("mov.b64 %0, {%1,%2};" : "=l"(r) : "f"(lo), "f"(hi)); return r;
}
__device__ __forceinline__ void unpack2(ull v, float &lo, float &hi) {
    asm("mov.b64 {%0,%1}, %2;" : "=f"(lo), "=f"(hi) : "l"(v));
}
__device__ __forceinline__ void fma2(ull &d, ull a, ull b) {
    asm("fma.rn.f32x2 %0, %1, %2, %0;" : "+l"(d) : "l"(a), "l"(b));
}
__device__ __forceinline__ ull add2(ull a, ull b) {
    ull r; asm("add.rn.f32x2 %0, %1, %2;" : "=l"(r) : "l"(a), "l"(b)); return r;
}

__global__ void __launch_bounds__(256, 2) attn_kernel(
    const float* __restrict__ S,
    const float* __restrict__ Wq,
    const float* __restrict__ bq,
    const float* __restrict__ Wk,
    const float* __restrict__ bk,
    float* __restrict__ out)
{
    __shared__ __align__(16) float sW[128 * 20];  // [n][h 0..15], row stride 20
    __shared__ float sBias[16];
    __shared__ float sQ[64 * 9];                  // q[row][h], stride 9
    __shared__ __align__(16) float sK[512];       // kflat with chunk swizzle

    const int t    = threadIdx.x;
    const int w    = t >> 5;
    const int lane = t & 31;

    // ---- stage W + bias ----
    for (int idx = t; idx < 2048; idx += 256) {
        int n = idx >> 4, h = idx & 15;
        sW[n * 20 + h] = (h < 8) ? Wq[n * 8 + h] : Wk[n * 8 + (h - 8)];
    }
    if (t < 16) sBias[t] = (t < 8) ? bq[t] : bk[t - 8];

    // ---- S: coalesced LDG.32, lane owns cols {lane + 32c}, warp owns rows {w + 8r} ----
    float sv[8][4];
    const float* Sb = S + (size_t)blockIdx.x * 8192 + w * 128 + lane;
    #pragma unroll
    for (int r = 0; r < 8; r++)
        #pragma unroll
        for (int c = 0; c < 4; c++)
            sv[r][c] = Sb[r * 1024 + c * 32];
    __syncthreads();

    // ---- projection: 4 passes of 4 h each (p=0,1 -> Q h0..7; p=2,3 -> K h8..15) ----
    for (int p = 0; p < 4; p++) {
        ull acc[16];
        #pragma unroll
        for (int k = 0; k < 16; k++) acc[k] = 0ull;

        #pragma unroll
        for (int c = 0; c < 4; c++) {
            float4 wv = *reinterpret_cast<const float4*>(sW + (lane + 32 * c) * 20 + 4 * p);
            ull w01 = pack2(wv.x, wv.y), w23 = pack2(wv.z, wv.w);
            #pragma unroll
            for (int r = 0; r < 8; r++) {
                ull ss = pack2(sv[r][c], sv[r][c]);
                fma2(acc[2 * r],     ss, w01);
                fma2(acc[2 * r + 1], ss, w23);
            }
        }

        // butterfly split-reduce over 32 lanes (n dimension)
        {
            const int kb = (lane & 16) ? 8 : 0, sb = 8 - kb;
            #pragma unroll
            for (int k = 0; k < 8; k++) {
                ull rcv = __shfl_xor_sync(0xffffffffu, acc[sb + k], 16);
                acc[k] = add2(acc[kb + k], rcv);
            }
        }
        {
            const int kb = (lane & 8) ? 4 : 0, sb = 4 - kb;
            #pragma unroll
            for (int k = 0; k < 4; k++) {
                ull rcv = __shfl_xor_sync(0xffffffffu, acc[sb + k], 8);
                acc[k] = add2(acc[kb + k], rcv);
            }
        }
        {
            const int kb = (lane & 4) ? 2 : 0, sb = 2 - kb;
            #pragma unroll
            for (int k = 0; k < 2; k++) {
                ull rcv = __shfl_xor_sync(0xffffffffu, acc[sb + k], 4);
                acc[k] = add2(acc[kb + k], rcv);
            }
        }
        {
            const int kb = (lane & 2) ? 1 : 0, sb = 1 - kb;
            ull rcv = __shfl_xor_sync(0xffffffffu, acc[sb], 2);
            acc[0] = add2(acc[kb], rcv);
        }
        acc[0] = add2(acc[0], __shfl_xor_sync(0xffffffffu, acc[0], 1));

        // lane -> (row, h-pair)
        const int rc  = (lane >> 1) & 15;
        const int rr  = rc >> 1, hp = rc & 1;
        const int h0  = 4 * p + 2 * hp;
        const int row = w + 8 * rr;
        float f0, f1; unpack2(acc[0], f0, f1);
        f0 += sBias[h0]; f1 += sBias[h0 + 1];
        if (!(lane & 1)) {
            if (p < 2) {
                sQ[row * 9 + h0]     = f0;
                sQ[row * 9 + h0 + 1] = f1;
            } else {
                // kflat[a*8 + h'] with 16B-chunk swizzle: chunk ^= (a>>3)&1
                int chunk = (p - 2) ^ ((row >> 3) & 1);
                *reinterpret_cast<float2*>(sK + row * 8 + chunk * 4 + 2 * hp)
                    = make_float2(f0, f1);
            }
        }
    }
    __syncthreads();

    // ---- phase 3: att tile, thread = (ig: 4 i-rows, jq: 4 j-cols) ----
    const int ig = t >> 4, jq = t & 15;
    ull accA[8];
    #pragma unroll
    for (int k = 0; k < 8; k++) accA[k] = 0ull;

    #pragma unroll
    for (int hx = 0; hx < 8; hx++) {
        // kres[hx][4jq .. 4jq+3] with swizzle compensation
        int a8    = 8 * hx + (jq >> 1);
        int chunk = (jq & 1) ^ (hx & 1);
        float4 kv = *reinterpret_cast<const float4*>(sK + a8 * 8 + chunk * 4);
        ull k01 = pack2(kv.x, kv.y), k23 = pack2(kv.z, kv.w);
        #pragma unroll
        for (int r = 0; r < 4; r++) {
            float qv = sQ[(4 * ig + r) * 9 + hx];
            ull qq = pack2(qv, qv);
            fma2(accA[2 * r],     qq, k01);
            fma2(accA[2 * r + 1], qq, k23);
        }
    }

    float v[4][4];
    #pragma unroll
    for (int r = 0; r < 4; r++) {
        unpack2(accA[2 * r],     v[r][0], v[r][1]);
        unpack2(accA[2 * r + 1], v[r][2], v[r][3]);
    }

    // ---- softmax over 16 jq lanes ----
    float mx[4], sm[4];
    #pragma unroll
    for (int r = 0; r < 4; r++)
        mx[r] = fmaxf(fmaxf(v[r][0], v[r][1]), fmaxf(v[r][2], v[r][3]));
    #pragma unroll
    for (int st = 1; st <= 8; st <<= 1)
        #pragma unroll
        for (int r = 0; r < 4; r++)
            mx[r] = fmaxf(mx[r], __shfl_xor_sync(0xffffffffu, mx[r], st));
    #pragma unroll
    for (int r = 0; r < 4; r++) {
        sm[r] = 0.f;
        #pragma unroll
        for (int p = 0; p < 4; p++) { v[r][p] = __expf(v[r][p] - mx[r]); sm[r] += v[r][p]; }
    }
    #pragma unroll
    for (int st = 1; st <= 8; st <<= 1)
        #pragma unroll
        for (int r = 0; r < 4; r++)
            sm[r] += __shfl_xor_sync(0xffffffffu, sm[r], st);

    // ---- diag-compacted direct store ----
    float* ob = out + (size_t)blockIdx.x * 4032;
    #pragma unroll
    for (int r = 0; r < 4; r++) {
        const int i = 4 * ig + r;
        float* orow = ob + i * 63;
        const float inv = __fdividef(1.0f, sm[r]);
        #pragma unroll
        for (int p = 0; p < 4; p++) {
            int j = 4 * jq + p;
            if (j != i) orow[j - (j > i)] = v[r][p] * inv;
        }
    }
}

extern "C" void kernel_launch(void* const* d_in, const int* in_sizes, int n_in,
                              void* d_out, int out_size)
{
    const float* S  = (const float*)d_in[0];
    const float* Wq = (const float*)d_in[1];
    const float* bq = (const float*)d_in[2];
    const float* Wk = (const float*)d_in[3];
    const float* bk = (const float*)d_in[4];
    int tb_total = in_sizes[0] / (64 * 128);   // 16384 tiles
    attn_kernel<<<tb_total, 256>>>(S, Wq, bq, Wk, bk, (float*)d_out);
}

// round 4
// speedup vs baseline: 2.2300x; 2.2300x over previous
#include <cuda_runtime.h>

typedef unsigned long long ull;

__device__ __forceinline__ ull pack2(float lo, float hi) {
    ull r; asm("mov.b64 %0, {%1,%2};" : "=l"(r) : "f"(lo), "f"(hi)); return r;
}
__device__ __forceinline__ void unpack2(ull v, float &lo, float &hi) {
    asm("mov.b64 {%0,%1}, %2;" : "=f"(lo), "=f"(hi) : "l"(v));
}
__device__ __forceinline__ void fma2(ull &d, ull a, ull b) {
    asm("fma.rn.f32x2 %0, %1, %2, %0;" : "+l"(d) : "l"(a), "l"(b));
}

__global__ void __launch_bounds__(256, 3) attn_kernel(
    const float* __restrict__ S,
    const float* __restrict__ Wq,
    const float* __restrict__ bq,
    const float* __restrict__ Wk,
    const float* __restrict__ bk,
    float* __restrict__ out)
{
    // sBig: phase1-2 = swizzled S tile (f4[64][32]); then partial-exchange (float2);
    //       then uncompacted output staging (stride 68).
    __shared__ __align__(16) float sBig[8192];
    __shared__ __align__(16) float sW[128 * 16];   // W row n: h0..7 = Wq, h8..15 = Wk
    __shared__ __align__(16) float sQ[64 * 12];    // q[a][h], stride 12
    __shared__ __align__(16) float sK[64 * 8];     // kflat[a*8+h]
    __shared__ float sBias[16];

    const int t = threadIdx.x;

    // ---- stage W + bias ----
    for (int idx = t; idx < 2048; idx += 256) {
        int n = idx >> 4, h = idx & 15;
        sW[idx] = (h < 8) ? Wq[n * 8 + h] : Wk[n * 8 + (h - 8)];
    }
    if (t < 16) sBias[t] = (t < 8) ? bq[t] : bk[t - 8];

    // ---- stage S: coalesced LDG.128 (one row per warp-instr), XOR chunk swizzle ----
    {
        const float4* Sg = reinterpret_cast<const float4*>(S + (size_t)blockIdx.x * 8192);
        float4* sS4 = reinterpret_cast<float4*>(sBig);
        #pragma unroll
        for (int k = 0; k < 8; k++) {
            int g   = t + 256 * k;      // global float4 index 0..2047
            int row = g >> 5;
            int c   = g & 31;
            sS4[row * 32 + (c ^ (row & 31))] = Sg[g];
        }
    }
    __syncthreads();

    // ---- phase 2: thread (a, qu) computes partial q,k over n = qu*32 .. +31 ----
    const int a  = t & 63;
    const int qu = t >> 6;
    ull acc[8];
    #pragma unroll
    for (int p = 0; p < 8; p++) acc[p] = 0ull;
    {
        const float4* sS4 = reinterpret_cast<const float4*>(sBig);
        #pragma unroll
        for (int i = 0; i < 8; i++) {
            float4 sv = sS4[a * 32 + ((qu * 8 + i) ^ (a & 31))];
            float sx[4] = {sv.x, sv.y, sv.z, sv.w};
            #pragma unroll
            for (int e = 0; e < 4; e++) {
                int n = qu * 32 + i * 4 + e;
                ull ss = pack2(sx[e], sx[e]);
                const ulonglong2* wrow = reinterpret_cast<const ulonglong2*>(sW + n * 16);
                ulonglong2 w0 = wrow[0], w1 = wrow[1], w2 = wrow[2], w3 = wrow[3];
                fma2(acc[0], ss, w0.x); fma2(acc[1], ss, w0.y);
                fma2(acc[2], ss, w1.x); fma2(acc[3], ss, w1.y);
                fma2(acc[4], ss, w2.x); fma2(acc[5], ss, w2.y);
                fma2(acc[6], ss, w3.x); fma2(acc[7], ss, w3.y);
            }
        }
    }
    __syncthreads();   // everyone done reading S before reusing sBig

    // ---- exchange partials: float2 [(qu*8+hp)*66 + a] ----
    {
        float2* sRed = reinterpret_cast<float2*>(sBig);
        #pragma unroll
        for (int hp = 0; hp < 8; hp++) {
            float lo, hi; unpack2(acc[hp], lo, hi);
            sRed[(qu * 8 + hp) * 66 + a] = make_float2(lo, hi);
        }
    }
    __syncthreads();

    // ---- reduce over qu, add bias, write sQ / sK ----
    {
        const int a2 = t >> 2, c = t & 3;   // h = 4c..4c+3; c<2 -> q, c>=2 -> k
        const float2* sRed = reinterpret_cast<const float2*>(sBig);
        float r0 = 0.f, r1 = 0.f, r2 = 0.f, r3 = 0.f;
        #pragma unroll
        for (int quu = 0; quu < 4; quu++) {
            float2 p0 = sRed[(quu * 8 + 2 * c    ) * 66 + a2];
            float2 p1 = sRed[(quu * 8 + 2 * c + 1) * 66 + a2];
            r0 += p0.x; r1 += p0.y; r2 += p1.x; r3 += p1.y;
        }
        r0 += sBias[4 * c + 0]; r1 += sBias[4 * c + 1];
        r2 += sBias[4 * c + 2]; r3 += sBias[4 * c + 3];
        if (c < 2)
            reinterpret_cast<float4*>(sQ)[a2 * 3 + c] = make_float4(r0, r1, r2, r3);
        else
            reinterpret_cast<float4*>(sK)[a2 * 2 + (c - 2)] = make_float4(r0, r1, r2, r3);
    }
    __syncthreads();

    // ---- phase 3: thread (i3 = t>>2, jg = t&3), cols j = 16m + 4jg + e ----
    const int i3 = t >> 2, jg = t & 3;
    ull accA[8];
    #pragma unroll
    for (int p = 0; p < 8; p++) accA[p] = 0ull;
    #pragma unroll
    for (int h = 0; h < 8; h++) {
        float qv = sQ[i3 * 12 + h];
        ull qq = pack2(qv, qv);
        #pragma unroll
        for (int m = 0; m < 4; m++) {
            // kres[h][j0..j0+3], j0 = 16m+4jg: flat f4 index = h*16 + 4m + jg
            ulonglong2 kv = reinterpret_cast<const ulonglong2*>(sK)[h * 16 + 4 * m + jg];
            fma2(accA[2 * m],     qq, kv.x);
            fma2(accA[2 * m + 1], qq, kv.y);
        }
    }
    float v[4][4];
    #pragma unroll
    for (int m = 0; m < 4; m++) {
        unpack2(accA[2 * m],     v[m][0], v[m][1]);
        unpack2(accA[2 * m + 1], v[m][2], v[m][3]);
    }

    // ---- softmax across the 4-lane row group ----
    float mx = v[0][0];
    #pragma unroll
    for (int m = 0; m < 4; m++)
        #pragma unroll
        for (int e = 0; e < 4; e++) mx = fmaxf(mx, v[m][e]);
    mx = fmaxf(mx, __shfl_xor_sync(0xffffffffu, mx, 1));
    mx = fmaxf(mx, __shfl_xor_sync(0xffffffffu, mx, 2));
    float sm = 0.f;
    #pragma unroll
    for (int m = 0; m < 4; m++)
        #pragma unroll
        for (int e = 0; e < 4; e++) { v[m][e] = __expf(v[m][e] - mx); sm += v[m][e]; }
    sm += __shfl_xor_sync(0xffffffffu, sm, 1);
    sm += __shfl_xor_sync(0xffffffffu, sm, 2);
    const float inv = __fdividef(1.0f, sm);

    // ---- stage normalized probs uncompacted, stride 68 ----
    {
        float4* sO4 = reinterpret_cast<float4*>(sBig);
        #pragma unroll
        for (int m = 0; m < 4; m++)
            sO4[i3 * 17 + 4 * m + jg] =
                make_float4(v[m][0] * inv, v[m][1] * inv, v[m][2] * inv, v[m][3] * inv);
    }
    __syncthreads();

    // ---- compacted coalesced copy to gmem ----
    {
        float* ob = out + (size_t)blockIdx.x * 4032;
        #pragma unroll
        for (int r = 0; r < 16; r++) {
            int o = t + 256 * r;
            if (o < 4032) {
                int i  = (o * 66577) >> 22;     // o / 63 (exact for o < 4096)
                int jc = o - 63 * i;
                ob[o] = sBig[i * 68 + jc + (jc >= i)];
            }
        }
    }
}

extern "C" void kernel_launch(void* const* d_in, const int* in_sizes, int n_in,
                              void* d_out, int out_size)
{
    const float* S  = (const float*)d_in[0];
    const float* Wq = (const float*)d_in[1];
    const float* bq = (const float*)d_in[2];
    const float* Wk = (const float*)d_in[3];
    const float* bk = (const float*)d_in[4];
    int tb_total = in_sizes[0] / (64 * 128);   // 16384 tiles
    attn_kernel<<<tb_total, 256>>>(S, Wq, bq, Wk, bk, (float*)d_out);
}

// round 5
// speedup vs baseline: 2.5972x; 1.1647x over previous
#include <cuda_runtime.h>

typedef unsigned long long ull;

__device__ __forceinline__ ull pack2(float lo, float hi) {
    ull r; asm("mov.b64 %0, {%1,%2};" : "=l"(r) : "f"(lo), "f"(hi)); return r;
}
__device__ __forceinline__ void unpack2(ull v, float &lo, float &hi) {
    asm("mov.b64 {%0,%1}, %2;" : "=f"(lo), "=f"(hi) : "l"(v));
}
__device__ __forceinline__ void fma2(ull &d, ull a, ull b) {
    asm("fma.rn.f32x2 %0, %1, %2, %0;" : "+l"(d) : "l"(a), "l"(b));
}

__global__ void __launch_bounds__(256, 3) attn_kernel(
    const float* __restrict__ S,
    const float* __restrict__ Wq,
    const float* __restrict__ bq,
    const float* __restrict__ Wk,
    const float* __restrict__ bk,
    float* __restrict__ out)
{
    // sBig: (1) XOR-swizzled S tile  (2) projection partials  (3) output staging
    __shared__ __align__(16) float sBig[8192];
    __shared__ __align__(16) float sW[128 * 16];   // [n][h]: h0..7=Wq, h8..15=Wk
    __shared__ __align__(16) float sQ[64 * 12];    // q[a][h0..7], f4 stride 3
    __shared__ __align__(16) float sK[64 * 12];    // kflat[a][h0..7], f4 stride 3
    __shared__ float sBias[16];

    const int t = threadIdx.x;
    const int w = t >> 5;
    const int l = t & 31;

    // ---- stage S (coalesced LDG.128, XOR chunk swizzle) + W + bias ----
    {
        const float4* Sg = reinterpret_cast<const float4*>(S + (size_t)blockIdx.x * 8192);
        float4* sS4 = reinterpret_cast<float4*>(sBig);
        #pragma unroll
        for (int k = 0; k < 8; k++) {
            int g = t + 256 * k;
            int row = g >> 5, c = g & 31;
            sS4[row * 32 + (c ^ (row & 31))] = Sg[g];
        }
    }
    for (int idx = t; idx < 2048; idx += 256) {
        int n = idx >> 4, h = idx & 15;
        sW[idx] = (h < 8) ? Wq[n * 8 + h] : Wk[n * 8 + (h - 8)];
    }
    if (t < 16) sBias[t] = (t < 8) ? bq[t] : bk[t - 8];
    __syncthreads();

    // ---- phase 2: warp w -> n in [16w, 16w+16); lane -> rows {l, l+32} ----
    ull acc[2][8];
    #pragma unroll
    for (int k2 = 0; k2 < 2; k2++)
        #pragma unroll
        for (int hp = 0; hp < 8; hp++) acc[k2][hp] = 0ull;
    {
        const float4* sS4 = reinterpret_cast<const float4*>(sBig);
        #pragma unroll
        for (int c4 = 0; c4 < 4; c4++) {
            float4 s0 = sS4[l * 32 + ((4 * w + c4) ^ l)];
            float4 s1 = sS4[(l + 32) * 32 + ((4 * w + c4) ^ l)];
            float a0[4] = {s0.x, s0.y, s0.z, s0.w};
            float a1[4] = {s1.x, s1.y, s1.z, s1.w};
            #pragma unroll
            for (int e = 0; e < 4; e++) {
                const ulonglong2* wp =
                    reinterpret_cast<const ulonglong2*>(sW + (16 * w + 4 * c4 + e) * 16);
                ulonglong2 w0 = wp[0], w1 = wp[1], w2 = wp[2], w3 = wp[3];
                ull sA = pack2(a0[e], a0[e]);
                ull sB = pack2(a1[e], a1[e]);
                fma2(acc[0][0], sA, w0.x); fma2(acc[0][1], sA, w0.y);
                fma2(acc[0][2], sA, w1.x); fma2(acc[0][3], sA, w1.y);
                fma2(acc[0][4], sA, w2.x); fma2(acc[0][5], sA, w2.y);
                fma2(acc[0][6], sA, w3.x); fma2(acc[0][7], sA, w3.y);
                fma2(acc[1][0], sB, w0.x); fma2(acc[1][1], sB, w0.y);
                fma2(acc[1][2], sB, w1.x); fma2(acc[1][3], sB, w1.y);
                fma2(acc[1][4], sB, w2.x); fma2(acc[1][5], sB, w2.y);
                fma2(acc[1][6], sB, w3.x); fma2(acc[1][7], sB, w3.y);
            }
        }
    }
    __syncthreads();   // all S reads done before sBig becomes the partial buffer

    // ---- exchange partials: ulonglong2 [(s*64 + row)*4 + (cp ^ ((row>>1)&3))] ----
    {
        ulonglong2* P = reinterpret_cast<ulonglong2*>(sBig);
        #pragma unroll
        for (int k2 = 0; k2 < 2; k2++) {
            int row = l + 32 * k2;
            #pragma unroll
            for (int cp = 0; cp < 4; cp++) {
                ulonglong2 vv;
                vv.x = acc[k2][2 * cp];
                vv.y = acc[k2][2 * cp + 1];
                P[(w * 64 + row) * 4 + (cp ^ ((row >> 1) & 3))] = vv;
            }
        }
    }
    __syncthreads();

    // ---- reduce over 8 slices, add bias, write sQ / sK ----
    {
        const int a2 = t >> 2, c = t & 3;    // c: h-group {4c..4c+3}; c<2 -> q, c>=2 -> k
        const ulonglong2* P = reinterpret_cast<const ulonglong2*>(sBig);
        float r0 = 0.f, r1 = 0.f, r2 = 0.f, r3 = 0.f;
        #pragma unroll
        for (int s = 0; s < 8; s++) {
            ulonglong2 vv = P[(s * 64 + a2) * 4 + (c ^ ((a2 >> 1) & 3))];
            float x0, x1, y0, y1;
            unpack2(vv.x, x0, x1);
            unpack2(vv.y, y0, y1);
            r0 += x0; r1 += x1; r2 += y0; r3 += y1;
        }
        r0 += sBias[4 * c + 0]; r1 += sBias[4 * c + 1];
        r2 += sBias[4 * c + 2]; r3 += sBias[4 * c + 3];
        if (c < 2)
            reinterpret_cast<float4*>(sQ)[a2 * 3 + c] = make_float4(r0, r1, r2, r3);
        else
            reinterpret_cast<float4*>(sK)[a2 * 3 + (c - 2)] = make_float4(r0, r1, r2, r3);
    }
    __syncthreads();

    // ---- phase 3: thread = (ig: rows {2ig, 2ig+1}, jg8: j in [8*jg8, 8*jg8+8)) ----
    const int ig = t >> 3, jg8 = t & 7;
    float q[2][8];
    #pragma unroll
    for (int r = 0; r < 2; r++) {
        float4 qa = reinterpret_cast<const float4*>(sQ)[(2 * ig + r) * 3];
        float4 qb = reinterpret_cast<const float4*>(sQ)[(2 * ig + r) * 3 + 1];
        q[r][0] = qa.x; q[r][1] = qa.y; q[r][2] = qa.z; q[r][3] = qa.w;
        q[r][4] = qb.x; q[r][5] = qb.y; q[r][6] = qb.z; q[r][7] = qb.w;
    }
    ull accA[2][4];
    #pragma unroll
    for (int r = 0; r < 2; r++)
        #pragma unroll
        for (int c = 0; c < 4; c++) accA[r][c] = 0ull;
    #pragma unroll
    for (int h = 0; h < 8; h++) {
        // kres[h][j] = kflat[h*64 + j]; row (8h + jg8) of sK holds kflat[(8h+jg8)*8 .. +7]
        const ulonglong2* kp = reinterpret_cast<const ulonglong2*>(sK);
        ulonglong2 k0 = kp[(8 * h + jg8) * 3];
        ulonglong2 k1 = kp[(8 * h + jg8) * 3 + 1];
        #pragma unroll
        for (int r = 0; r < 2; r++) {
            ull qq = pack2(q[r][h], q[r][h]);
            fma2(accA[r][0], qq, k0.x); fma2(accA[r][1], qq, k0.y);
            fma2(accA[r][2], qq, k1.x); fma2(accA[r][3], qq, k1.y);
        }
    }
    float v[2][8];
    #pragma unroll
    for (int r = 0; r < 2; r++) {
        unpack2(accA[r][0], v[r][0], v[r][1]);
        unpack2(accA[r][1], v[r][2], v[r][3]);
        unpack2(accA[r][2], v[r][4], v[r][5]);
        unpack2(accA[r][3], v[r][6], v[r][7]);
    }

    // ---- softmax over the 8 jg8 lanes ----
    float inv[2];
    #pragma unroll
    for (int r = 0; r < 2; r++) {
        float mx = v[r][0];
        #pragma unroll
        for (int p = 1; p < 8; p++) mx = fmaxf(mx, v[r][p]);
        mx = fmaxf(mx, __shfl_xor_sync(0xffffffffu, mx, 1));
        mx = fmaxf(mx, __shfl_xor_sync(0xffffffffu, mx, 2));
        mx = fmaxf(mx, __shfl_xor_sync(0xffffffffu, mx, 4));
        float sm = 0.f;
        #pragma unroll
        for (int p = 0; p < 8; p++) { v[r][p] = __expf(v[r][p] - mx); sm += v[r][p]; }
        sm += __shfl_xor_sync(0xffffffffu, sm, 1);
        sm += __shfl_xor_sync(0xffffffffu, sm, 2);
        sm += __shfl_xor_sync(0xffffffffu, sm, 4);
        inv[r] = __fdividef(1.0f, sm);
    }

    // ---- stage normalized probs uncompacted, f4 stride 18 (72 floats/row) ----
    {
        float4* sO4 = reinterpret_cast<float4*>(sBig);
        #pragma unroll
        for (int r = 0; r < 2; r++) {
            int row = 2 * ig + r;
            sO4[row * 18 + 2 * jg8 + 0] =
                make_float4(v[r][0] * inv[r], v[r][1] * inv[r],
                            v[r][2] * inv[r], v[r][3] * inv[r]);
            sO4[row * 18 + 2 * jg8 + 1] =
                make_float4(v[r][4] * inv[r], v[r][5] * inv[r],
                            v[r][6] * inv[r], v[r][7] * inv[r]);
        }
    }
    __syncthreads();

    // ---- compacted coalesced copy to gmem ----
    {
        float* ob = out + (size_t)blockIdx.x * 4032;
        #pragma unroll
        for (int k = 0; k < 16; k++) {
            int o = t + 256 * k;
            if (o < 4032) {
                int i  = (o * 66577) >> 22;     // o / 63, exact for o < 4096
                int jc = o - 63 * i;
                ob[o] = sBig[i * 72 + jc + (jc >= i)];
            }
        }
    }
}

extern "C" void kernel_launch(void* const* d_in, const int* in_sizes, int n_in,
                              void* d_out, int out_size)
{
    const float* S  = (const float*)d_in[0];
    const float* Wq = (const float*)d_in[1];
    const float* bq = (const float*)d_in[2];
    const float* Wk = (const float*)d_in[3];
    const float* bk = (const float*)d_in[4];
    int tb_total = in_sizes[0] / (64 * 128);   // 16384 tiles
    attn_kernel<<<tb_total, 256>>>(S, Wq, bq, Wk, bk, (float*)d_out);
}

// round 6
// speedup vs baseline: 2.6439x; 1.0180x over previous
#include <cuda_runtime.h>

typedef unsigned long long ull;

__device__ __forceinline__ ull pack2(float lo, float hi) {
    ull r; asm("mov.b64 %0, {%1,%2};" : "=l"(r) : "f"(lo), "f"(hi)); return r;
}
__device__ __forceinline__ void unpack2(ull v, float &lo, float &hi) {
    asm("mov.b64 {%0,%1}, %2;" : "=f"(lo), "=f"(hi) : "l"(v));
}
__device__ __forceinline__ void fma2(ull &d, ull a, ull b) {
    asm("fma.rn.f32x2 %0, %1, %2, %0;" : "+l"(d) : "l"(a), "l"(b));
}

__global__ void __launch_bounds__(256, 4) attn_kernel(
    const float* __restrict__ S,
    const float* __restrict__ Wq,
    const float* __restrict__ bq,
    const float* __restrict__ Wk,
    const float* __restrict__ bk,
    float* __restrict__ out)
{
    // sBig: (1) XOR-swizzled S tile  (2) projection partials  (3) output staging
    __shared__ __align__(16) float sBig[8192];
    __shared__ __align__(16) float sW[128 * 16];   // [n][h]: h0..7=Wq, h8..15=Wk
    __shared__ __align__(16) float sQ[64 * 12];    // q[a][h0..7], f4 stride 3
    __shared__ __align__(16) float sK[64 * 12];    // kflat[a][h0..7], f4 stride 3
    __shared__ float sBias[16];

    const int t = threadIdx.x;
    const int w = t >> 5;
    const int l = t & 31;

    // ---- stage S (coalesced LDG.128, XOR chunk swizzle) + W + bias ----
    {
        const float4* Sg = reinterpret_cast<const float4*>(S + (size_t)blockIdx.x * 8192);
        float4* sS4 = reinterpret_cast<float4*>(sBig);
        #pragma unroll
        for (int k = 0; k < 8; k++) {
            int g = t + 256 * k;
            int row = g >> 5, c = g & 31;
            sS4[row * 32 + (c ^ (row & 31))] = Sg[g];
        }
    }
    for (int idx = t; idx < 2048; idx += 256) {
        int n = idx >> 4, h = idx & 15;
        sW[idx] = (h < 8) ? Wq[n * 8 + h] : Wk[n * 8 + (h - 8)];
    }
    if (t < 16) sBias[t] = (t < 8) ? bq[t] : bk[t - 8];
    __syncthreads();

    // ---- preload this thread's S: rows {l, l+32}, chunks 4w..4w+3 ----
    float4 sv[2][4];
    {
        const float4* sS4 = reinterpret_cast<const float4*>(sBig);
        #pragma unroll
        for (int k2 = 0; k2 < 2; k2++)
            #pragma unroll
            for (int c4 = 0; c4 < 4; c4++)
                sv[k2][c4] = sS4[(l + 32 * k2) * 32 + ((4 * w + c4) ^ l)];
    }
    __syncthreads();   // all S reads done; sBig becomes the partial buffer

    // ---- phase 2: two h-halves (0: Q h0..7, 1: K h8..15), 8 accs each ----
    {
        ulonglong2* P = reinterpret_cast<ulonglong2*>(sBig);
        #pragma unroll
        for (int half = 0; half < 2; half++) {
            ull acc[2][4];
            #pragma unroll
            for (int k2 = 0; k2 < 2; k2++)
                #pragma unroll
                for (int p = 0; p < 4; p++) acc[k2][p] = 0ull;

            #pragma unroll
            for (int c4 = 0; c4 < 4; c4++) {
                float a0[4] = {sv[0][c4].x, sv[0][c4].y, sv[0][c4].z, sv[0][c4].w};
                float a1[4] = {sv[1][c4].x, sv[1][c4].y, sv[1][c4].z, sv[1][c4].w};
                #pragma unroll
                for (int e = 0; e < 4; e++) {
                    const ulonglong2* wp = reinterpret_cast<const ulonglong2*>(
                        sW + (16 * w + 4 * c4 + e) * 16);
                    ulonglong2 w0 = wp[2 * half];
                    ulonglong2 w1 = wp[2 * half + 1];
                    ull sA = pack2(a0[e], a0[e]);
                    ull sB = pack2(a1[e], a1[e]);
                    fma2(acc[0][0], sA, w0.x); fma2(acc[0][1], sA, w0.y);
                    fma2(acc[0][2], sA, w1.x); fma2(acc[0][3], sA, w1.y);
                    fma2(acc[1][0], sB, w0.x); fma2(acc[1][1], sB, w0.y);
                    fma2(acc[1][2], sB, w1.x); fma2(acc[1][3], sB, w1.y);
                }
            }

            // write this half's partials (XOR-swizzled chunk index)
            #pragma unroll
            for (int k2 = 0; k2 < 2; k2++) {
                int row = l + 32 * k2;
                #pragma unroll
                for (int p = 0; p < 2; p++) {
                    ulonglong2 vv;
                    vv.x = acc[k2][2 * p];
                    vv.y = acc[k2][2 * p + 1];
                    P[(w * 64 + row) * 4 + ((2 * half + p) ^ ((row >> 1) & 3))] = vv;
                }
            }
        }
    }
    __syncthreads();

    // ---- reduce over 8 slices, add bias, write sQ / sK ----
    {
        const int a2 = t >> 2, c = t & 3;    // c: h-group {4c..4c+3}; c<2 -> q, c>=2 -> k
        const ulonglong2* P = reinterpret_cast<const ulonglong2*>(sBig);
        float r0 = 0.f, r1 = 0.f, r2 = 0.f, r3 = 0.f;
        #pragma unroll
        for (int s = 0; s < 8; s++) {
            ulonglong2 vv = P[(s * 64 + a2) * 4 + (c ^ ((a2 >> 1) & 3))];
            float x0, x1, y0, y1;
            unpack2(vv.x, x0, x1);
            unpack2(vv.y, y0, y1);
            r0 += x0; r1 += x1; r2 += y0; r3 += y1;
        }
        r0 += sBias[4 * c + 0]; r1 += sBias[4 * c + 1];
        r2 += sBias[4 * c + 2]; r3 += sBias[4 * c + 3];
        if (c < 2)
            reinterpret_cast<float4*>(sQ)[a2 * 3 + c] = make_float4(r0, r1, r2, r3);
        else
            reinterpret_cast<float4*>(sK)[a2 * 3 + (c - 2)] = make_float4(r0, r1, r2, r3);
    }
    __syncthreads();

    // ---- phase 3: thread = (ig: rows {2ig, 2ig+1}, jg8: j in [8*jg8, 8*jg8+8)) ----
    const int ig = t >> 3, jg8 = t & 7;
    float q[2][8];
    #pragma unroll
    for (int r = 0; r < 2; r++) {
        float4 qa = reinterpret_cast<const float4*>(sQ)[(2 * ig + r) * 3];
        float4 qb = reinterpret_cast<const float4*>(sQ)[(2 * ig + r) * 3 + 1];
        q[r][0] = qa.x; q[r][1] = qa.y; q[r][2] = qa.z; q[r][3] = qa.w;
        q[r][4] = qb.x; q[r][5] = qb.y; q[r][6] = qb.z; q[r][7] = qb.w;
    }
    ull accA[2][4];
    #pragma unroll
    for (int r = 0; r < 2; r++)
        #pragma unroll
        for (int c = 0; c < 4; c++) accA[r][c] = 0ull;
    #pragma unroll
    for (int h = 0; h < 8; h++) {
        const ulonglong2* kp = reinterpret_cast<const ulonglong2*>(sK);
        ulonglong2 k0 = kp[(8 * h + jg8) * 3];
        ulonglong2 k1 = kp[(8 * h + jg8) * 3 + 1];
        #pragma unroll
        for (int r = 0; r < 2; r++) {
            ull qq = pack2(q[r][h], q[r][h]);
            fma2(accA[r][0], qq, k0.x); fma2(accA[r][1], qq, k0.y);
            fma2(accA[r][2], qq, k1.x); fma2(accA[r][3], qq, k1.y);
        }
    }
    float v[2][8];
    #pragma unroll
    for (int r = 0; r < 2; r++) {
        unpack2(accA[r][0], v[r][0], v[r][1]);
        unpack2(accA[r][1], v[r][2], v[r][3]);
        unpack2(accA[r][2], v[r][4], v[r][5]);
        unpack2(accA[r][3], v[r][6], v[r][7]);
    }

    // ---- softmax over the 8 jg8 lanes ----
    float inv[2];
    #pragma unroll
    for (int r = 0; r < 2; r++) {
        float mx = v[r][0];
        #pragma unroll
        for (int p = 1; p < 8; p++) mx = fmaxf(mx, v[r][p]);
        mx = fmaxf(mx, __shfl_xor_sync(0xffffffffu, mx, 1));
        mx = fmaxf(mx, __shfl_xor_sync(0xffffffffu, mx, 2));
        mx = fmaxf(mx, __shfl_xor_sync(0xffffffffu, mx, 4));
        float sm = 0.f;
        #pragma unroll
        for (int p = 0; p < 8; p++) { v[r][p] = __expf(v[r][p] - mx); sm += v[r][p]; }
        sm += __shfl_xor_sync(0xffffffffu, sm, 1);
        sm += __shfl_xor_sync(0xffffffffu, sm, 2);
        sm += __shfl_xor_sync(0xffffffffu, sm, 4);
        inv[r] = __fdividef(1.0f, sm);
    }

    // ---- stage normalized probs uncompacted, f4 stride 18 (72 floats/row) ----
    {
        float4* sO4 = reinterpret_cast<float4*>(sBig);
        #pragma unroll
        for (int r = 0; r < 2; r++) {
            int row = 2 * ig + r;
            sO4[row * 18 + 2 * jg8 + 0] =
                make_float4(v[r][0] * inv[r], v[r][1] * inv[r],
                            v[r][2] * inv[r], v[r][3] * inv[r]);
            sO4[row * 18 + 2 * jg8 + 1] =
                make_float4(v[r][4] * inv[r], v[r][5] * inv[r],
                            v[r][6] * inv[r], v[r][7] * inv[r]);
        }
    }
    __syncthreads();

    // ---- compacted copy: gather 4 scalars -> one STG.128 ----
    {
        float4* ob4 = reinterpret_cast<float4*>(out + (size_t)blockIdx.x * 4032);
        #pragma unroll
        for (int k = 0; k < 4; k++) {
            int o4 = t + 256 * k;
            if (o4 < 1008) {
                float r[4];
                #pragma unroll
                for (int e = 0; e < 4; e++) {
                    int o  = 4 * o4 + e;
                    int i  = (o * 66577) >> 22;     // o / 63, exact for o < 4096
                    int jc = o - 63 * i;
                    r[e] = sBig[i * 72 + jc + (jc >= i)];
                }
                ob4[o4] = make_float4(r[0], r[1], r[2], r[3]);
            }
        }
    }
}

extern "C" void kernel_launch(void* const* d_in, const int* in_sizes, int n_in,
                              void* d_out, int out_size)
{
    const float* S  = (const float*)d_in[0];
    const float* Wq = (const float*)d_in[1];
    const float* bq = (const float*)d_in[2];
    const float* Wk = (const float*)d_in[3];
    const float* bk = (const float*)d_in[4];
    int tb_total = in_sizes[0] / (64 * 128);   // 16384 tiles
    attn_kernel<<<tb_total, 256>>>(S, Wq, bq, Wk, bk, (float*)d_out);
}